// round 1
// baseline (speedup 1.0000x reference)
#include <cuda_runtime.h>
#include <cstddef>

#define D 256
#define N_MAX 100000

// Scratch (allocation-free rule: __device__ globals)
__device__ float g_neigh[(size_t)N_MAX * D];
__device__ float g_deg[N_MAX];
__device__ float g_invdeg[N_MAX];

// ---------------------------------------------------------------------------
__global__ void zero_neigh_kernel(int n4) {
    int i = blockIdx.x * blockDim.x + threadIdx.x;
    if (i < n4) ((float4*)g_neigh)[i] = make_float4(0.f, 0.f, 0.f, 0.f);
}

__global__ void zero_deg_kernel(int n) {
    int i = blockIdx.x * blockDim.x + threadIdx.x;
    if (i < n) g_deg[i] = 0.f;
}

__global__ void deg_kernel(const int* __restrict__ dst, int E) {
    int i = blockIdx.x * blockDim.x + threadIdx.x;
    if (i < E) atomicAdd(&g_deg[dst[i]], 1.0f);
}

__global__ void invdeg_kernel(int n) {
    int i = blockIdx.x * blockDim.x + threadIdx.x;
    if (i < n) {
        float d = g_deg[i];
        g_invdeg[i] = (d > 0.f) ? (1.0f / d) : 0.f;
    }
}

__global__ void copy_kernel(const float* __restrict__ in, float* __restrict__ out, int n4) {
    int i = blockIdx.x * blockDim.x + threadIdx.x;
    if (i < n4) ((float4*)out)[i] = ((const float4*)in)[i];
}

// ---------------------------------------------------------------------------
// One warp per edge: gather a 256-float row from X[src], scale by invdeg[dst],
// vector-reduce into g_neigh[dst]. invdeg is folded in here (distributes over sum).
__global__ void scatter_kernel(const float* __restrict__ X,
                               const int* __restrict__ src,
                               const int* __restrict__ dst, int E) {
    int e = blockIdx.x * 8 + (threadIdx.x >> 5);
    if (e >= E) return;
    int lane = threadIdx.x & 31;

    int s = __ldg(src + e);
    int d = __ldg(dst + e);
    float w = __ldg(&g_invdeg[d]);

    const float4* xr = (const float4*)(X + (size_t)s * D);
    float4* nr = ((float4*)g_neigh) + (size_t)d * (D / 4);

#pragma unroll
    for (int i = 0; i < 2; ++i) {
        float4 v = __ldg(xr + lane + 32 * i);
        asm volatile("red.global.add.v4.f32 [%0], {%1, %2, %3, %4};"
                     :: "l"(nr + lane + 32 * i),
                        "f"(v.x * w), "f"(v.y * w), "f"(v.z * w), "f"(v.w * w)
                     : "memory");
    }
}

// ---------------------------------------------------------------------------
// Fused dual-GEMM: out[M,256] = X @ Ws + g_neigh @ Wn + bias, optional relu.
// Tile: BM=64, BN=64, BK=16; 256 threads; 4x4 register micro-tile per thread.
__global__ void __launch_bounds__(256) linear_kernel(
    const float* __restrict__ X,
    const float* __restrict__ Ws,
    const float* __restrict__ Wn,
    const float* __restrict__ bias,
    float* __restrict__ out,
    int M, int do_relu) {
    __shared__ float As[16][65];  // [k][m], padded to dodge STS bank conflicts
    __shared__ float Bs[16][64];  // [k][n], rows 16B-aligned for LDS.128

    int tid = threadIdx.x;
    int bm = blockIdx.y * 64;
    int bn = blockIdx.x * 64;

    int arow = tid >> 2;          // 0..63
    int acol = (tid & 3) * 4;     // 0,4,8,12
    int brow = tid >> 4;          // 0..15
    int bcol = (tid & 15) * 4;    // 0..60
    int ty = tid >> 4;            // 0..15
    int tx = tid & 15;            // 0..15

    int grow = bm + arow;
    float acc[4][4] = {};

#pragma unroll 1
    for (int phase = 0; phase < 2; ++phase) {
        const float* A = phase ? g_neigh : X;
        const float* W = phase ? Wn : Ws;

#pragma unroll 1
        for (int k0 = 0; k0 < 256; k0 += 16) {
            float4 av = make_float4(0.f, 0.f, 0.f, 0.f);
            if (grow < M)
                av = __ldg((const float4*)(A + (size_t)grow * 256 + k0 + acol));
            As[acol + 0][arow] = av.x;
            As[acol + 1][arow] = av.y;
            As[acol + 2][arow] = av.z;
            As[acol + 3][arow] = av.w;

            float4 wv = __ldg((const float4*)(W + (size_t)(k0 + brow) * 256 + bn + bcol));
            *(float4*)&Bs[brow][bcol] = wv;

            __syncthreads();

#pragma unroll
            for (int k = 0; k < 16; ++k) {
                float a0 = As[k][ty * 4 + 0];
                float a1 = As[k][ty * 4 + 1];
                float a2 = As[k][ty * 4 + 2];
                float a3 = As[k][ty * 4 + 3];
                float4 bv = *(const float4*)&Bs[k][tx * 4];
                acc[0][0] += a0 * bv.x; acc[0][1] += a0 * bv.y;
                acc[0][2] += a0 * bv.z; acc[0][3] += a0 * bv.w;
                acc[1][0] += a1 * bv.x; acc[1][1] += a1 * bv.y;
                acc[1][2] += a1 * bv.z; acc[1][3] += a1 * bv.w;
                acc[2][0] += a2 * bv.x; acc[2][1] += a2 * bv.y;
                acc[2][2] += a2 * bv.z; acc[2][3] += a2 * bv.w;
                acc[3][0] += a3 * bv.x; acc[3][1] += a3 * bv.y;
                acc[3][2] += a3 * bv.z; acc[3][3] += a3 * bv.w;
            }
            __syncthreads();
        }
    }

    float4 bb = __ldg((const float4*)(bias + bn + tx * 4));
#pragma unroll
    for (int i = 0; i < 4; ++i) {
        int row = bm + ty * 4 + i;
        if (row < M) {
            float4 o;
            o.x = acc[i][0] + bb.x;
            o.y = acc[i][1] + bb.y;
            o.z = acc[i][2] + bb.z;
            o.w = acc[i][3] + bb.w;
            if (do_relu) {
                o.x = fmaxf(o.x, 0.f);
                o.y = fmaxf(o.y, 0.f);
                o.z = fmaxf(o.z, 0.f);
                o.w = fmaxf(o.w, 0.f);
            }
            *(float4*)(out + (size_t)row * 256 + bn + tx * 4) = o;
        }
    }
}

// ---------------------------------------------------------------------------
extern "C" void kernel_launch(void* const* d_in, const int* in_sizes, int n_in,
                              void* d_out, int out_size) {
    const float* feat = (const float*)d_in[0];
    const int*   src  = (const int*)d_in[1];
    const int*   dst  = (const int*)d_in[2];
    const float* Ws0  = (const float*)d_in[3];
    const float* Wn0  = (const float*)d_in[4];
    const float* b0   = (const float*)d_in[5];
    const float* Ws1  = (const float*)d_in[6];
    const float* Wn1  = (const float*)d_in[7];
    const float* b1   = (const float*)d_in[8];

    int N = in_sizes[0] / D;   // 100000
    int E = in_sizes[1];       // 1600000

    float* out0 = (float*)d_out;                       // x0
    float* a1   = out0 + (size_t)N * D;                // relu(sage1)
    float* h2   = out0 + 2 * (size_t)N * D;            // sage2

    int nd4 = N * (D / 4);

    // out[0] = feat
    copy_kernel<<<(nd4 + 255) / 256, 256>>>(feat, out0, nd4);

    // degree + inverse degree
    zero_deg_kernel<<<(N + 255) / 256, 256>>>(N);
    deg_kernel<<<(E + 255) / 256, 256>>>(dst, E);
    invdeg_kernel<<<(N + 255) / 256, 256>>>(N);

    dim3 lgrid(D / 64, (N + 63) / 64);

    // Layer 1
    zero_neigh_kernel<<<(nd4 + 255) / 256, 256>>>(nd4);
    scatter_kernel<<<(E + 7) / 8, 256>>>(feat, src, dst, E);
    linear_kernel<<<lgrid, 256>>>(feat, Ws0, Wn0, b0, a1, N, 1);

    // Layer 2
    zero_neigh_kernel<<<(nd4 + 255) / 256, 256>>>(nd4);
    scatter_kernel<<<(E + 7) / 8, 256>>>(a1, src, dst, E);
    linear_kernel<<<lgrid, 256>>>(a1, Ws1, Wn1, b1, h2, N, 0);
}

// round 4
// speedup vs baseline: 1.2646x; 1.2646x over previous
#include <cuda_runtime.h>
#include <cstddef>
#include <cstdint>

#define D 256
#define N_MAX 100000

// Scratch (allocation-free rule: __device__ globals)
__device__ float g_neigh[(size_t)N_MAX * D];
__device__ float g_deg[N_MAX];
__device__ float g_invdeg[N_MAX];

// ---------------------------------------------------------------------------
__global__ void zero_neigh_kernel(int n4) {
    int i = blockIdx.x * blockDim.x + threadIdx.x;
    if (i < n4) ((float4*)g_neigh)[i] = make_float4(0.f, 0.f, 0.f, 0.f);
}

__global__ void zero_deg_kernel(int n) {
    int i = blockIdx.x * blockDim.x + threadIdx.x;
    if (i < n) g_deg[i] = 0.f;
}

__global__ void deg_kernel(const int* __restrict__ dst, int E) {
    int i = blockIdx.x * blockDim.x + threadIdx.x;
    if (i < E) atomicAdd(&g_deg[dst[i]], 1.0f);
}

__global__ void invdeg_kernel(int n) {
    int i = blockIdx.x * blockDim.x + threadIdx.x;
    if (i < n) {
        float d = g_deg[i];
        g_invdeg[i] = (d > 0.f) ? (1.0f / d) : 0.f;
    }
}

__global__ void copy_kernel(const float* __restrict__ in, float* __restrict__ out, int n4) {
    int i = blockIdx.x * blockDim.x + threadIdx.x;
    if (i < n4) ((float4*)out)[i] = ((const float4*)in)[i];
}

// ---------------------------------------------------------------------------
// One warp per edge: gather a 256-float row from X[src], scale by invdeg[dst],
// vector-reduce into g_neigh[dst].
__global__ void scatter_kernel(const float* __restrict__ X,
                               const int* __restrict__ src,
                               const int* __restrict__ dst, int E) {
    int e = blockIdx.x * 8 + (threadIdx.x >> 5);
    if (e >= E) return;
    int lane = threadIdx.x & 31;

    int s = __ldg(src + e);
    int d = __ldg(dst + e);
    float w = __ldg(&g_invdeg[d]);

    const float4* xr = (const float4*)(X + (size_t)s * D);
    float4* nr = ((float4*)g_neigh) + (size_t)d * (D / 4);

#pragma unroll
    for (int i = 0; i < 2; ++i) {
        float4 v = __ldg(xr + lane + 32 * i);
        asm volatile("red.global.add.v4.f32 [%0], {%1, %2, %3, %4};"
                     :: "l"(nr + lane + 32 * i),
                        "f"(v.x * w), "f"(v.y * w), "f"(v.z * w), "f"(v.w * w)
                     : "memory");
    }
}

// ---------------------------------------------------------------------------
// 3xTF32 tensor-core GEMM: out[M,256] = [X | g_neigh] @ [Ws ; Wn] + bias.
// Each fp32 operand split hi/lo via cvt.rna.tf32; acc += ah*bh + ah*bl + al*bh.
// BM=128, BN=64, BK=32; 256 threads (8 warps, 4x2); warp tile 32x32.

#define A_STR 36
#define B_STR 72
#define SA_SZ (128 * A_STR)           // words per stage
#define SB_SZ (32 * B_STR)
#define SMEM_BYTES ((2 * SA_SZ + 2 * SB_SZ) * 4)

__device__ __forceinline__ void cp_async16(void* s, const void* g, bool pred) {
    uint32_t sa = (uint32_t)__cvta_generic_to_shared(s);
    int sz = pred ? 16 : 0;
    asm volatile("cp.async.cg.shared.global [%0], [%1], 16, %2;"
                 :: "r"(sa), "l"(g), "r"(sz) : "memory");
}

__device__ __forceinline__ void mma_tf32(float* c, const uint32_t* a, const uint32_t* b) {
    asm volatile(
        "mma.sync.aligned.m16n8k8.row.col.f32.tf32.tf32.f32 "
        "{%0,%1,%2,%3}, {%4,%5,%6,%7}, {%8,%9}, {%0,%1,%2,%3};"
        : "+f"(c[0]), "+f"(c[1]), "+f"(c[2]), "+f"(c[3])
        : "r"(a[0]), "r"(a[1]), "r"(a[2]), "r"(a[3]), "r"(b[0]), "r"(b[1]));
}

__device__ __forceinline__ void split_tf32(float x, uint32_t& hi, uint32_t& lo) {
    uint32_t h;
    asm("cvt.rna.tf32.f32 %0, %1;" : "=r"(h) : "f"(x));
    float r = x - __uint_as_float(h);
    asm("cvt.rna.tf32.f32 %0, %1;" : "=r"(lo) : "f"(r));
    hi = h;
}

__global__ void __launch_bounds__(256) sage_gemm_kernel(
    const float* __restrict__ X,     // [M,256] self features
    const float* __restrict__ Ws,    // [256,256]
    const float* __restrict__ Wn,    // [256,256]
    const float* __restrict__ bias,  // [256]
    float* __restrict__ out,         // [M,256]
    int M, int do_relu) {
    extern __shared__ float smem[];
    float* sA = smem;                 // 2 stages of [128][A_STR]
    float* sB = smem + 2 * SA_SZ;     // 2 stages of [32][B_STR]

    const int tid = threadIdx.x;
    const int lane = tid & 31;
    const int wid = tid >> 5;
    const int wm = wid >> 1;          // 0..3
    const int wn = wid & 1;           // 0..1
    const int bm = blockIdx.y * 128;
    const int bn = blockIdx.x * 64;

    float acc[2][4][4] = {};

    // ---- tile loader (cp.async) ----
    auto load_tile = [&](int it, int buf) {
        int kg = it * 32;
        const float* Aptr = (kg < 256) ? X : (const float*)g_neigh;  // device symbol!
        const float* Wptr = (kg < 256) ? Ws : Wn;
        int kl = kg & 255;
        float* dA = sA + buf * SA_SZ;
        float* dB = sB + buf * SB_SZ;
#pragma unroll
        for (int i = 0; i < 4; ++i) {
            int ci = i * 256 + tid;
            int row = ci >> 3, ch = ci & 7;
            int grow = bm + row;
            bool ok = grow < M;
            int crow = ok ? grow : (M - 1);
            const float* g = Aptr + (size_t)crow * 256 + kl + ch * 4;
            cp_async16(dA + row * A_STR + ch * 4, g, ok);
        }
#pragma unroll
        for (int i = 0; i < 2; ++i) {
            int ci = i * 256 + tid;
            int row = ci >> 4, ch = ci & 15;
            const float* g = Wptr + (size_t)(kl + row) * 256 + bn + ch * 4;
            cp_async16(dB + row * B_STR + ch * 4, g, true);
        }
    };

    load_tile(0, 0);
    asm volatile("cp.async.commit_group;" ::: "memory");

    const int K_ITERS = 512 / 32;  // 16
#pragma unroll 1
    for (int it = 0; it < K_ITERS; ++it) {
        if (it + 1 < K_ITERS) {
            load_tile(it + 1, (it + 1) & 1);
            asm volatile("cp.async.commit_group;" ::: "memory");
            asm volatile("cp.async.wait_group 1;" ::: "memory");
        } else {
            asm volatile("cp.async.wait_group 0;" ::: "memory");
        }
        __syncthreads();

        const float* A = sA + (it & 1) * SA_SZ;
        const float* B = sB + (it & 1) * SB_SZ;

#pragma unroll
        for (int ks = 0; ks < 4; ++ks) {
            int kk = ks * 8 + (lane & 3);
            uint32_t ah[2][4], al[2][4], bh[4][2], bl[4][2];
#pragma unroll
            for (int mt = 0; mt < 2; ++mt) {
                int r = wm * 32 + mt * 16 + (lane >> 2);
                split_tf32(A[r * A_STR + kk],           ah[mt][0], al[mt][0]);
                split_tf32(A[(r + 8) * A_STR + kk],     ah[mt][1], al[mt][1]);
                split_tf32(A[r * A_STR + kk + 4],       ah[mt][2], al[mt][2]);
                split_tf32(A[(r + 8) * A_STR + kk + 4], ah[mt][3], al[mt][3]);
            }
#pragma unroll
            for (int nt = 0; nt < 4; ++nt) {
                int n = wn * 32 + nt * 8 + (lane >> 2);
                split_tf32(B[kk * B_STR + n],       bh[nt][0], bl[nt][0]);
                split_tf32(B[(kk + 4) * B_STR + n], bh[nt][1], bl[nt][1]);
            }
#pragma unroll
            for (int mt = 0; mt < 2; ++mt)
#pragma unroll
                for (int nt = 0; nt < 4; ++nt) {
                    mma_tf32(acc[mt][nt], al[mt], bh[nt]);  // small terms first
                    mma_tf32(acc[mt][nt], ah[mt], bl[nt]);
                    mma_tf32(acc[mt][nt], ah[mt], bh[nt]);
                }
        }
        __syncthreads();
    }

    // ---- epilogue: bias (+relu), float2 stores ----
#pragma unroll
    for (int mt = 0; mt < 2; ++mt) {
        int r0 = bm + wm * 32 + mt * 16 + (lane >> 2);
#pragma unroll
        for (int nt = 0; nt < 4; ++nt) {
            int c = bn + wn * 32 + nt * 8 + (lane & 3) * 2;
            float bx = __ldg(bias + c);
            float by = __ldg(bias + c + 1);
            float2 v0, v1;
            v0.x = acc[mt][nt][0] + bx; v0.y = acc[mt][nt][1] + by;
            v1.x = acc[mt][nt][2] + bx; v1.y = acc[mt][nt][3] + by;
            if (do_relu) {
                v0.x = fmaxf(v0.x, 0.f); v0.y = fmaxf(v0.y, 0.f);
                v1.x = fmaxf(v1.x, 0.f); v1.y = fmaxf(v1.y, 0.f);
            }
            if (r0 < M)     *(float2*)(out + (size_t)r0 * 256 + c) = v0;
            if (r0 + 8 < M) *(float2*)(out + (size_t)(r0 + 8) * 256 + c) = v1;
        }
    }
}

// ---------------------------------------------------------------------------
extern "C" void kernel_launch(void* const* d_in, const int* in_sizes, int n_in,
                              void* d_out, int out_size) {
    const float* feat = (const float*)d_in[0];
    const int*   src  = (const int*)d_in[1];
    const int*   dst  = (const int*)d_in[2];
    const float* Ws0  = (const float*)d_in[3];
    const float* Wn0  = (const float*)d_in[4];
    const float* b0   = (const float*)d_in[5];
    const float* Ws1  = (const float*)d_in[6];
    const float* Wn1  = (const float*)d_in[7];
    const float* b1   = (const float*)d_in[8];

    int N = in_sizes[0] / D;   // 100000
    int E = in_sizes[1];       // 1600000

    float* out0 = (float*)d_out;                       // x0
    float* a1   = out0 + (size_t)N * D;                // relu(sage1)
    float* h2   = out0 + 2 * (size_t)N * D;            // sage2

    int nd4 = N * (D / 4);

    cudaFuncSetAttribute(sage_gemm_kernel,
                         cudaFuncAttributeMaxDynamicSharedMemorySize, SMEM_BYTES);

    // out[0] = feat
    copy_kernel<<<(nd4 + 255) / 256, 256>>>(feat, out0, nd4);

    // degree + inverse degree
    zero_deg_kernel<<<(N + 255) / 256, 256>>>(N);
    deg_kernel<<<(E + 255) / 256, 256>>>(dst, E);
    invdeg_kernel<<<(N + 255) / 256, 256>>>(N);

    dim3 ggrid(D / 64, (N + 127) / 128);

    // Layer 1
    zero_neigh_kernel<<<(nd4 + 255) / 256, 256>>>(nd4);
    scatter_kernel<<<(E + 7) / 8, 256>>>(feat, src, dst, E);
    sage_gemm_kernel<<<ggrid, 256, SMEM_BYTES>>>(feat, Ws0, Wn0, b0, a1, N, 1);

    // Layer 2
    zero_neigh_kernel<<<(nd4 + 255) / 256, 256>>>(nd4);
    scatter_kernel<<<(E + 7) / 8, 256>>>(a1, src, dst, E);
    sage_gemm_kernel<<<ggrid, 256, SMEM_BYTES>>>(a1, Ws1, Wn1, b1, h2, N, 0);
}

// round 5
// speedup vs baseline: 1.8200x; 1.4393x over previous
#include <cuda_runtime.h>
#include <cstddef>
#include <cstdint>

#define D 256
#define N_MAX 100000
#define E_MAX 1600000
#define SCAN_BLK 1024

// Scratch (allocation-free rule: __device__ globals)
__device__ float g_neigh[(size_t)N_MAX * D];
__device__ int g_cnt[N_MAX];
__device__ int g_off[N_MAX + 1];
__device__ int g_cursor[N_MAX];
__device__ int g_bsum[(N_MAX + SCAN_BLK - 1) / SCAN_BLK + 1];
__device__ int g_esrc[E_MAX];

// ---------------------------------------------------------------------------
__global__ void zero_cnt_kernel(int n) {
    int i = blockIdx.x * blockDim.x + threadIdx.x;
    if (i < n) g_cnt[i] = 0;
}

__global__ void hist_kernel(const int* __restrict__ dst, int E) {
    int i = blockIdx.x * blockDim.x + threadIdx.x;
    if (i < E) atomicAdd(&g_cnt[dst[i]], 1);
}

// Block-level exclusive scan (Hillis-Steele inclusive, then subtract self)
__global__ void scan_blocks_kernel(int n) {
    __shared__ int sm[SCAN_BLK];
    int tid = threadIdx.x;
    int i = blockIdx.x * SCAN_BLK + tid;
    int v = (i < n) ? g_cnt[i] : 0;
    sm[tid] = v;
    __syncthreads();
#pragma unroll
    for (int off = 1; off < SCAN_BLK; off <<= 1) {
        int t = (tid >= off) ? sm[tid - off] : 0;
        __syncthreads();
        sm[tid] += t;
        __syncthreads();
    }
    if (i < n) g_off[i] = sm[tid] - v;
    if (tid == SCAN_BLK - 1) g_bsum[blockIdx.x] = sm[tid];
}

__global__ void scan_bsums_kernel(int nb) {
    if (threadIdx.x == 0 && blockIdx.x == 0) {
        int run = 0;
        for (int b = 0; b < nb; ++b) {
            int t = g_bsum[b];
            g_bsum[b] = run;
            run += t;
        }
    }
}

__global__ void scan_add_kernel(int n, int E) {
    int i = blockIdx.x * blockDim.x + threadIdx.x;
    if (i < n) {
        int v = g_off[i] + g_bsum[i >> 10];
        g_off[i] = v;
        g_cursor[i] = v;
    }
    if (i == 0) g_off[n] = E;
}

__global__ void fill_kernel(const int* __restrict__ src,
                            const int* __restrict__ dst, int E) {
    int e = blockIdx.x * blockDim.x + threadIdx.x;
    if (e < E) {
        int d = dst[e];
        int p = atomicAdd(&g_cursor[d], 1);
        g_esrc[p] = src[e];
    }
}

__global__ void copy_kernel(const float* __restrict__ in, float* __restrict__ out, int n4) {
    int i = blockIdx.x * blockDim.x + threadIdx.x;
    if (i < n4) ((float4*)out)[i] = ((const float4*)in)[i];
}

// ---------------------------------------------------------------------------
// Gather aggregation: one warp per dst node. Sum X[src] rows over the CSR
// in-edge list in registers (2-edge unroll for MLP), scale by 1/deg, one store.
__global__ void gather_kernel(const float* __restrict__ X, int N) {
    int node = blockIdx.x * 8 + (threadIdx.x >> 5);
    if (node >= N) return;
    int lane = threadIdx.x & 31;

    int beg = g_off[node];
    int end = g_off[node + 1];

    float4 a0 = make_float4(0.f, 0.f, 0.f, 0.f);
    float4 a1 = make_float4(0.f, 0.f, 0.f, 0.f);

    int i = beg;
    for (; i + 1 < end; i += 2) {
        int s0 = __ldg(g_esrc + i);
        int s1 = __ldg(g_esrc + i + 1);
        const float4* x0 = (const float4*)(X + (size_t)s0 * D);
        const float4* x1 = (const float4*)(X + (size_t)s1 * D);
        float4 v00 = __ldg(x0 + lane);
        float4 v01 = __ldg(x0 + lane + 32);
        float4 v10 = __ldg(x1 + lane);
        float4 v11 = __ldg(x1 + lane + 32);
        a0.x += v00.x + v10.x; a0.y += v00.y + v10.y;
        a0.z += v00.z + v10.z; a0.w += v00.w + v10.w;
        a1.x += v01.x + v11.x; a1.y += v01.y + v11.y;
        a1.z += v01.z + v11.z; a1.w += v01.w + v11.w;
    }
    if (i < end) {
        int s0 = __ldg(g_esrc + i);
        const float4* x0 = (const float4*)(X + (size_t)s0 * D);
        float4 v00 = __ldg(x0 + lane);
        float4 v01 = __ldg(x0 + lane + 32);
        a0.x += v00.x; a0.y += v00.y; a0.z += v00.z; a0.w += v00.w;
        a1.x += v01.x; a1.y += v01.y; a1.z += v01.z; a1.w += v01.w;
    }

    float inv = (end > beg) ? (1.0f / (float)(end - beg)) : 0.f;
    a0.x *= inv; a0.y *= inv; a0.z *= inv; a0.w *= inv;
    a1.x *= inv; a1.y *= inv; a1.z *= inv; a1.w *= inv;

    float4* nr = ((float4*)g_neigh) + (size_t)node * (D / 4);
    nr[lane] = a0;
    nr[lane + 32] = a1;
}

// ---------------------------------------------------------------------------
// 3xTF32 tensor-core GEMM: out[M,256] = [X | g_neigh] @ [Ws ; Wn] + bias.
#define A_STR 36
#define B_STR 72
#define SA_SZ (128 * A_STR)
#define SB_SZ (32 * B_STR)
#define SMEM_BYTES ((2 * SA_SZ + 2 * SB_SZ) * 4)

__device__ __forceinline__ void cp_async16(void* s, const void* g, bool pred) {
    uint32_t sa = (uint32_t)__cvta_generic_to_shared(s);
    int sz = pred ? 16 : 0;
    asm volatile("cp.async.cg.shared.global [%0], [%1], 16, %2;"
                 :: "r"(sa), "l"(g), "r"(sz) : "memory");
}

__device__ __forceinline__ void mma_tf32(float* c, const uint32_t* a, const uint32_t* b) {
    asm volatile(
        "mma.sync.aligned.m16n8k8.row.col.f32.tf32.tf32.f32 "
        "{%0,%1,%2,%3}, {%4,%5,%6,%7}, {%8,%9}, {%0,%1,%2,%3};"
        : "+f"(c[0]), "+f"(c[1]), "+f"(c[2]), "+f"(c[3])
        : "r"(a[0]), "r"(a[1]), "r"(a[2]), "r"(a[3]), "r"(b[0]), "r"(b[1]));
}

__device__ __forceinline__ void split_tf32(float x, uint32_t& hi, uint32_t& lo) {
    uint32_t h;
    asm("cvt.rna.tf32.f32 %0, %1;" : "=r"(h) : "f"(x));
    float r = x - __uint_as_float(h);
    asm("cvt.rna.tf32.f32 %0, %1;" : "=r"(lo) : "f"(r));
    hi = h;
}

__global__ void __launch_bounds__(256) sage_gemm_kernel(
    const float* __restrict__ X,
    const float* __restrict__ Ws,
    const float* __restrict__ Wn,
    const float* __restrict__ bias,
    float* __restrict__ out,
    int M, int do_relu) {
    extern __shared__ float smem[];
    float* sA = smem;
    float* sB = smem + 2 * SA_SZ;

    const int tid = threadIdx.x;
    const int lane = tid & 31;
    const int wid = tid >> 5;
    const int wm = wid >> 1;
    const int wn = wid & 1;
    const int bm = blockIdx.y * 128;
    const int bn = blockIdx.x * 64;

    float acc[2][4][4] = {};

    auto load_tile = [&](int it, int buf) {
        int kg = it * 32;
        const float* Aptr = (kg < 256) ? X : (const float*)g_neigh;  // device symbol!
        const float* Wptr = (kg < 256) ? Ws : Wn;
        int kl = kg & 255;
        float* dA = sA + buf * SA_SZ;
        float* dB = sB + buf * SB_SZ;
#pragma unroll
        for (int i = 0; i < 4; ++i) {
            int ci = i * 256 + tid;
            int row = ci >> 3, ch = ci & 7;
            int grow = bm + row;
            bool ok = grow < M;
            int crow = ok ? grow : (M - 1);
            const float* g = Aptr + (size_t)crow * 256 + kl + ch * 4;
            cp_async16(dA + row * A_STR + ch * 4, g, ok);
        }
#pragma unroll
        for (int i = 0; i < 2; ++i) {
            int ci = i * 256 + tid;
            int row = ci >> 4, ch = ci & 15;
            const float* g = Wptr + (size_t)(kl + row) * 256 + bn + ch * 4;
            cp_async16(dB + row * B_STR + ch * 4, g, true);
        }
    };

    load_tile(0, 0);
    asm volatile("cp.async.commit_group;" ::: "memory");

    const int K_ITERS = 512 / 32;
#pragma unroll 1
    for (int it = 0; it < K_ITERS; ++it) {
        if (it + 1 < K_ITERS) {
            load_tile(it + 1, (it + 1) & 1);
            asm volatile("cp.async.commit_group;" ::: "memory");
            asm volatile("cp.async.wait_group 1;" ::: "memory");
        } else {
            asm volatile("cp.async.wait_group 0;" ::: "memory");
        }
        __syncthreads();

        const float* A = sA + (it & 1) * SA_SZ;
        const float* B = sB + (it & 1) * SB_SZ;

#pragma unroll
        for (int ks = 0; ks < 4; ++ks) {
            int kk = ks * 8 + (lane & 3);
            uint32_t ah[2][4], al[2][4], bh[4][2], bl[4][2];
#pragma unroll
            for (int mt = 0; mt < 2; ++mt) {
                int r = wm * 32 + mt * 16 + (lane >> 2);
                split_tf32(A[r * A_STR + kk],           ah[mt][0], al[mt][0]);
                split_tf32(A[(r + 8) * A_STR + kk],     ah[mt][1], al[mt][1]);
                split_tf32(A[r * A_STR + kk + 4],       ah[mt][2], al[mt][2]);
                split_tf32(A[(r + 8) * A_STR + kk + 4], ah[mt][3], al[mt][3]);
            }
#pragma unroll
            for (int nt = 0; nt < 4; ++nt) {
                int n = wn * 32 + nt * 8 + (lane >> 2);
                split_tf32(B[kk * B_STR + n],       bh[nt][0], bl[nt][0]);
                split_tf32(B[(kk + 4) * B_STR + n], bh[nt][1], bl[nt][1]);
            }
#pragma unroll
            for (int mt = 0; mt < 2; ++mt)
#pragma unroll
                for (int nt = 0; nt < 4; ++nt) {
                    mma_tf32(acc[mt][nt], al[mt], bh[nt]);
                    mma_tf32(acc[mt][nt], ah[mt], bl[nt]);
                    mma_tf32(acc[mt][nt], ah[mt], bh[nt]);
                }
        }
        __syncthreads();
    }

#pragma unroll
    for (int mt = 0; mt < 2; ++mt) {
        int r0 = bm + wm * 32 + mt * 16 + (lane >> 2);
#pragma unroll
        for (int nt = 0; nt < 4; ++nt) {
            int c = bn + wn * 32 + nt * 8 + (lane & 3) * 2;
            float bx = __ldg(bias + c);
            float by = __ldg(bias + c + 1);
            float2 v0, v1;
            v0.x = acc[mt][nt][0] + bx; v0.y = acc[mt][nt][1] + by;
            v1.x = acc[mt][nt][2] + bx; v1.y = acc[mt][nt][3] + by;
            if (do_relu) {
                v0.x = fmaxf(v0.x, 0.f); v0.y = fmaxf(v0.y, 0.f);
                v1.x = fmaxf(v1.x, 0.f); v1.y = fmaxf(v1.y, 0.f);
            }
            if (r0 < M)     *(float2*)(out + (size_t)r0 * 256 + c) = v0;
            if (r0 + 8 < M) *(float2*)(out + (size_t)(r0 + 8) * 256 + c) = v1;
        }
    }
}

// ---------------------------------------------------------------------------
extern "C" void kernel_launch(void* const* d_in, const int* in_sizes, int n_in,
                              void* d_out, int out_size) {
    const float* feat = (const float*)d_in[0];
    const int*   src  = (const int*)d_in[1];
    const int*   dst  = (const int*)d_in[2];
    const float* Ws0  = (const float*)d_in[3];
    const float* Wn0  = (const float*)d_in[4];
    const float* b0   = (const float*)d_in[5];
    const float* Ws1  = (const float*)d_in[6];
    const float* Wn1  = (const float*)d_in[7];
    const float* b1   = (const float*)d_in[8];

    int N = in_sizes[0] / D;   // 100000
    int E = in_sizes[1];       // 1600000

    float* out0 = (float*)d_out;
    float* a1   = out0 + (size_t)N * D;
    float* h2   = out0 + 2 * (size_t)N * D;

    int nd4 = N * (D / 4);
    int nb = (N + SCAN_BLK - 1) / SCAN_BLK;

    cudaFuncSetAttribute(sage_gemm_kernel,
                         cudaFuncAttributeMaxDynamicSharedMemorySize, SMEM_BYTES);

    // ---- CSR build (once per call; shared by both layers) ----
    zero_cnt_kernel<<<(N + 255) / 256, 256>>>(N);
    hist_kernel<<<(E + 255) / 256, 256>>>(dst, E);
    scan_blocks_kernel<<<nb, SCAN_BLK>>>(N);
    scan_bsums_kernel<<<1, 32>>>(nb);
    scan_add_kernel<<<(N + 255) / 256, 256>>>(N, E);
    fill_kernel<<<(E + 255) / 256, 256>>>(src, dst, E);

    dim3 ggrid(D / 64, (N + 127) / 128);

    // Layer 1
    gather_kernel<<<(N + 7) / 8, 256>>>(feat, N);
    sage_gemm_kernel<<<ggrid, 256, SMEM_BYTES>>>(feat, Ws0, Wn0, b0, a1, N, 1);

    // Layer 2
    gather_kernel<<<(N + 7) / 8, 256>>>(a1, N);
    sage_gemm_kernel<<<ggrid, 256, SMEM_BYTES>>>(a1, Ws1, Wn1, b1, h2, N, 0);

    // out[0] = feat (no deps; last so heavy kernels sit earlier in ncu's window)
    copy_kernel<<<(nd4 + 255) / 256, 256>>>(feat, out0, nd4);
}

// round 6
// speedup vs baseline: 2.5689x; 1.4114x over previous
#include <cuda_runtime.h>
#include <cuda_bf16.h>
#include <cstddef>
#include <cstdint>

#define D 256
#define N_MAX 100000
#define E_MAX 1600000
#define SCAN_BLK 1024

// ---- scratch (__device__ globals; allocation-free rule) ----
__device__ uint32_t g_feat_hi[(size_t)N_MAX * 128];  // bf16x2 words, [row][128]
__device__ uint32_t g_feat_lo[(size_t)N_MAX * 128];
__device__ uint32_t g_a1_hi[(size_t)N_MAX * 128];
__device__ uint32_t g_a1_lo[(size_t)N_MAX * 128];
__device__ uint32_t g_nhi[(size_t)N_MAX * 128];
__device__ uint32_t g_nlo[(size_t)N_MAX * 128];
__device__ uint32_t g_wthi[2][256 * 256];            // W^T: [n][512k as 256 words]
__device__ uint32_t g_wtlo[2][256 * 256];
__device__ int g_cnt[N_MAX];
__device__ int g_off[N_MAX + 1];
__device__ int g_cursor[N_MAX];
__device__ int g_bsum[(N_MAX + SCAN_BLK - 1) / SCAN_BLK + 1];
__device__ int g_esrc[E_MAX];

// ---- bf16 split helpers ----
__device__ __forceinline__ void split1(float x, float& h, float& l) {
    h = __bfloat162float(__float2bfloat16(x));
    l = x - h;
}
__device__ __forceinline__ uint32_t pack2(float lo_elem, float hi_elem) {
    __nv_bfloat162 t = __floats2bfloat162_rn(lo_elem, hi_elem);  // .x = low half
    return *reinterpret_cast<uint32_t*>(&t);
}
// split a float4 (4 consecutive k) into 2 hi-words and 2 lo-words
__device__ __forceinline__ void split4(float4 v, uint32_t* hw, uint32_t* lw) {
    float h0, l0, h1, l1, h2, l2, h3, l3;
    split1(v.x, h0, l0); split1(v.y, h1, l1);
    split1(v.z, h2, l2); split1(v.w, h3, l3);
    hw[0] = pack2(h0, h1); hw[1] = pack2(h2, h3);
    lw[0] = pack2(l0, l1); lw[1] = pack2(l2, l3);
}

// ---------------------------------------------------------------------------
__global__ void zero_cnt_kernel(int n) {
    int i = blockIdx.x * blockDim.x + threadIdx.x;
    if (i < n) g_cnt[i] = 0;
}
__global__ void hist_kernel(const int* __restrict__ dst, int E) {
    int i = blockIdx.x * blockDim.x + threadIdx.x;
    if (i < E) atomicAdd(&g_cnt[dst[i]], 1);
}
__global__ void scan_blocks_kernel(int n) {
    __shared__ int sm[SCAN_BLK];
    int tid = threadIdx.x;
    int i = blockIdx.x * SCAN_BLK + tid;
    int v = (i < n) ? g_cnt[i] : 0;
    sm[tid] = v;
    __syncthreads();
#pragma unroll
    for (int off = 1; off < SCAN_BLK; off <<= 1) {
        int t = (tid >= off) ? sm[tid - off] : 0;
        __syncthreads();
        sm[tid] += t;
        __syncthreads();
    }
    if (i < n) g_off[i] = sm[tid] - v;
    if (tid == SCAN_BLK - 1) g_bsum[blockIdx.x] = sm[tid];
}
__global__ void scan_bsums_kernel(int nb) {
    if (threadIdx.x == 0 && blockIdx.x == 0) {
        int run = 0;
        for (int b = 0; b < nb; ++b) { int t = g_bsum[b]; g_bsum[b] = run; run += t; }
    }
}
__global__ void scan_add_kernel(int n, int E) {
    int i = blockIdx.x * blockDim.x + threadIdx.x;
    if (i < n) {
        int v = g_off[i] + g_bsum[i >> 10];
        g_off[i] = v;
        g_cursor[i] = v;
    }
    if (i == 0) g_off[n] = E;
}
__global__ void fill_kernel(const int* __restrict__ src,
                            const int* __restrict__ dst, int E) {
    int e = blockIdx.x * blockDim.x + threadIdx.x;
    if (e < E) {
        int d = dst[e];
        int p = atomicAdd(&g_cursor[d], 1);
        g_esrc[p] = src[e];
    }
}

// copy feat -> out[0] AND split to g_feat_hi/lo
__global__ void copy_convert_kernel(const float* __restrict__ in,
                                    float* __restrict__ out, int n4) {
    int i = blockIdx.x * blockDim.x + threadIdx.x;
    if (i >= n4) return;
    float4 v = ((const float4*)in)[i];
    ((float4*)out)[i] = v;
    uint32_t hw[2], lw[2];
    split4(v, hw, lw);
    *(uint2*)&g_feat_hi[(size_t)i * 2] = make_uint2(hw[0], hw[1]);
    *(uint2*)&g_feat_lo[(size_t)i * 2] = make_uint2(lw[0], lw[1]);
}

// transpose + split weights: combined [512 K][256 N] -> Wt[n][256 words]
__global__ void wconv_kernel(const float* __restrict__ Ws,
                             const float* __restrict__ Wn, int layer) {
    int idx = blockIdx.x * blockDim.x + threadIdx.x;  // 65536 words
    if (idx >= 256 * 256) return;
    int n = idx & 255;
    int wp = idx >> 8;
    int k0 = wp * 2, k1 = k0 + 1;
    float v0 = (k0 < 256) ? Ws[k0 * 256 + n] : Wn[(k0 - 256) * 256 + n];
    float v1 = (k1 < 256) ? Ws[k1 * 256 + n] : Wn[(k1 - 256) * 256 + n];
    float h0, l0, h1, l1;
    split1(v0, h0, l0);
    split1(v1, h1, l1);
    g_wthi[layer][n * 256 + wp] = pack2(h0, h1);
    g_wtlo[layer][n * 256 + wp] = pack2(l0, l1);
}

// ---------------------------------------------------------------------------
// Gather aggregation: one warp per dst node; outputs bf16 hi/lo words.
__global__ void gather_kernel(const float* __restrict__ X, int N) {
    int node = blockIdx.x * 8 + (threadIdx.x >> 5);
    if (node >= N) return;
    int lane = threadIdx.x & 31;

    int beg = g_off[node];
    int end = g_off[node + 1];

    float4 a0 = make_float4(0.f, 0.f, 0.f, 0.f);
    float4 a1 = make_float4(0.f, 0.f, 0.f, 0.f);

    int i = beg;
    for (; i + 1 < end; i += 2) {
        int s0 = __ldg(g_esrc + i);
        int s1 = __ldg(g_esrc + i + 1);
        const float4* x0 = (const float4*)(X + (size_t)s0 * D);
        const float4* x1 = (const float4*)(X + (size_t)s1 * D);
        float4 v00 = __ldg(x0 + lane);
        float4 v01 = __ldg(x0 + lane + 32);
        float4 v10 = __ldg(x1 + lane);
        float4 v11 = __ldg(x1 + lane + 32);
        a0.x += v00.x + v10.x; a0.y += v00.y + v10.y;
        a0.z += v00.z + v10.z; a0.w += v00.w + v10.w;
        a1.x += v01.x + v11.x; a1.y += v01.y + v11.y;
        a1.z += v01.z + v11.z; a1.w += v01.w + v11.w;
    }
    if (i < end) {
        int s0 = __ldg(g_esrc + i);
        const float4* x0 = (const float4*)(X + (size_t)s0 * D);
        float4 v00 = __ldg(x0 + lane);
        float4 v01 = __ldg(x0 + lane + 32);
        a0.x += v00.x; a0.y += v00.y; a0.z += v00.z; a0.w += v00.w;
        a1.x += v01.x; a1.y += v01.y; a1.z += v01.z; a1.w += v01.w;
    }

    float inv = (end > beg) ? (1.0f / (float)(end - beg)) : 0.f;
    a0.x *= inv; a0.y *= inv; a0.z *= inv; a0.w *= inv;
    a1.x *= inv; a1.y *= inv; a1.z *= inv; a1.w *= inv;

    uint32_t hw[2], lw[2];
    size_t base = (size_t)node * 128;
    split4(a0, hw, lw);
    *(uint2*)&g_nhi[base + lane * 2] = make_uint2(hw[0], hw[1]);
    *(uint2*)&g_nlo[base + lane * 2] = make_uint2(lw[0], lw[1]);
    split4(a1, hw, lw);
    *(uint2*)&g_nhi[base + 64 + lane * 2] = make_uint2(hw[0], hw[1]);
    *(uint2*)&g_nlo[base + 64 + lane * 2] = make_uint2(lw[0], lw[1]);
}

// ---------------------------------------------------------------------------
// Split-BF16 tensor GEMM: out[M,256] = [X | NH] @ Wt^T + bias.
// 3 products: AhBh + AhBl + AlBh (error ~2^-16).
// BM=128, BN=64, BK=32 halves (2 x k16 steps); 8 warps (4x2), warp tile 32x32.
// smem rows padded to 20 b32 words (16B-aligned pad, conflict-free LDS).

#define T_STR 20
#define SA_SZ (128 * T_STR)   // words per A array per stage
#define SB_SZ (64 * T_STR)
#define SMEM_WORDS (2 * (2 * SA_SZ + 2 * SB_SZ))
#define SMEM_BYTES (SMEM_WORDS * 4)

__device__ __forceinline__ void cp_async16(void* s, const void* g, bool pred) {
    uint32_t sa = (uint32_t)__cvta_generic_to_shared(s);
    int sz = pred ? 16 : 0;
    asm volatile("cp.async.cg.shared.global [%0], [%1], 16, %2;"
                 :: "r"(sa), "l"(g), "r"(sz) : "memory");
}

__device__ __forceinline__ void mma_bf16(float* c, const uint32_t* a, const uint32_t* b) {
    asm volatile(
        "mma.sync.aligned.m16n8k16.row.col.f32.bf16.bf16.f32 "
        "{%0,%1,%2,%3}, {%4,%5,%6,%7}, {%8,%9}, {%0,%1,%2,%3};"
        : "+f"(c[0]), "+f"(c[1]), "+f"(c[2]), "+f"(c[3])
        : "r"(a[0]), "r"(a[1]), "r"(a[2]), "r"(a[3]), "r"(b[0]), "r"(b[1]));
}

__global__ void __launch_bounds__(256) sage_gemm_kernel(
    const float* __restrict__ bias,
    float* __restrict__ out,
    int M, int layer, int do_relu) {
    extern __shared__ uint32_t smem[];
    uint32_t* sAh = smem;                    // 2 stages x [128][T_STR]
    uint32_t* sAl = smem + 2 * SA_SZ;
    uint32_t* sBh = smem + 4 * SA_SZ;        // 2 stages x [64][T_STR]
    uint32_t* sBl = smem + 4 * SA_SZ + 2 * SB_SZ;

    const int tid = threadIdx.x;
    const int lane = tid & 31;
    const int wid = tid >> 5;
    const int wm = wid >> 1;
    const int wn = wid & 1;
    const int bm = blockIdx.y * 128;
    const int bn = blockIdx.x * 64;

    const uint32_t* Xhi = layer ? g_a1_hi : g_feat_hi;
    const uint32_t* Xlo = layer ? g_a1_lo : g_feat_lo;
    const uint32_t* Whi = g_wthi[layer];
    const uint32_t* Wlo = g_wtlo[layer];

    float acc[2][4][4] = {};

    auto load_tile = [&](int it, int buf) {
        int kg = it * 32;                      // k offset in halves (0..480)
        const uint32_t* Ah = (kg < 256) ? Xhi : (const uint32_t*)g_nhi;
        const uint32_t* Al = (kg < 256) ? Xlo : (const uint32_t*)g_nlo;
        int klw = (kg & 255) >> 1;             // word offset within row (0..112)
        uint32_t* dAh = sAh + buf * SA_SZ;
        uint32_t* dAl = sAl + buf * SA_SZ;
        uint32_t* dBh = sBh + buf * SB_SZ;
        uint32_t* dBl = sBl + buf * SB_SZ;
#pragma unroll
        for (int i = 0; i < 2; ++i) {          // A: 128 rows x 4 16B-chunks
            int ci = i * 256 + tid;
            int row = ci >> 2, ch = ci & 3;
            int grow = bm + row;
            bool ok = grow < M;
            size_t off = (size_t)(ok ? grow : (M - 1)) * 128 + klw + ch * 4;
            cp_async16(dAh + row * T_STR + ch * 4, Ah + off, ok);
            cp_async16(dAl + row * T_STR + ch * 4, Al + off, ok);
        }
        {                                      // B: 64 rows x 4 chunks
            int row = tid >> 2, ch = tid & 3;
            size_t off = (size_t)(bn + row) * 256 + it * 16 + ch * 4;
            cp_async16(dBh + row * T_STR + ch * 4, Whi + off, true);
            cp_async16(dBl + row * T_STR + ch * 4, Wlo + off, true);
        }
    };

    load_tile(0, 0);
    asm volatile("cp.async.commit_group;" ::: "memory");

    const int K_ITERS = 512 / 32;  // 16
#pragma unroll 1
    for (int it = 0; it < K_ITERS; ++it) {
        if (it + 1 < K_ITERS) {
            load_tile(it + 1, (it + 1) & 1);
            asm volatile("cp.async.commit_group;" ::: "memory");
            asm volatile("cp.async.wait_group 1;" ::: "memory");
        } else {
            asm volatile("cp.async.wait_group 0;" ::: "memory");
        }
        __syncthreads();

        const uint32_t* Ah = sAh + (it & 1) * SA_SZ;
        const uint32_t* Al = sAl + (it & 1) * SA_SZ;
        const uint32_t* Bh = sBh + (it & 1) * SB_SZ;
        const uint32_t* Bl = sBl + (it & 1) * SB_SZ;

#pragma unroll
        for (int ks = 0; ks < 2; ++ks) {       // two k16 steps per BK=32
            int c = ks * 8 + (lane & 3);
            uint32_t ah[2][4], al[2][4], bh[4][2], bl[4][2];
#pragma unroll
            for (int mt = 0; mt < 2; ++mt) {
                int r = wm * 32 + mt * 16 + (lane >> 2);
                ah[mt][0] = Ah[r * T_STR + c];
                ah[mt][1] = Ah[(r + 8) * T_STR + c];
                ah[mt][2] = Ah[r * T_STR + c + 4];
                ah[mt][3] = Ah[(r + 8) * T_STR + c + 4];
                al[mt][0] = Al[r * T_STR + c];
                al[mt][1] = Al[(r + 8) * T_STR + c];
                al[mt][2] = Al[r * T_STR + c + 4];
                al[mt][3] = Al[(r + 8) * T_STR + c + 4];
            }
#pragma unroll
            for (int nt = 0; nt < 4; ++nt) {
                int n = wn * 32 + nt * 8 + (lane >> 2);
                bh[nt][0] = Bh[n * T_STR + c];
                bh[nt][1] = Bh[n * T_STR + c + 4];
                bl[nt][0] = Bl[n * T_STR + c];
                bl[nt][1] = Bl[n * T_STR + c + 4];
            }
#pragma unroll
            for (int mt = 0; mt < 2; ++mt)
#pragma unroll
                for (int nt = 0; nt < 4; ++nt) {
                    mma_bf16(acc[mt][nt], ah[mt], bl[nt]);  // small terms first
                    mma_bf16(acc[mt][nt], al[mt], bh[nt]);
                    mma_bf16(acc[mt][nt], ah[mt], bh[nt]);
                }
        }
        __syncthreads();
    }

    // ---- epilogue: bias (+relu); layer 0 also writes a1 hi/lo bf16 ----
#pragma unroll
    for (int mt = 0; mt < 2; ++mt) {
        int r0 = bm + wm * 32 + mt * 16 + (lane >> 2);
#pragma unroll
        for (int nt = 0; nt < 4; ++nt) {
            int cc = bn + wn * 32 + nt * 8 + (lane & 3) * 2;
            float bx = __ldg(bias + cc);
            float by = __ldg(bias + cc + 1);
            float2 v0, v1;
            v0.x = acc[mt][nt][0] + bx; v0.y = acc[mt][nt][1] + by;
            v1.x = acc[mt][nt][2] + bx; v1.y = acc[mt][nt][3] + by;
            if (do_relu) {
                v0.x = fmaxf(v0.x, 0.f); v0.y = fmaxf(v0.y, 0.f);
                v1.x = fmaxf(v1.x, 0.f); v1.y = fmaxf(v1.y, 0.f);
            }
            if (r0 < M) {
                *(float2*)(out + (size_t)r0 * 256 + cc) = v0;
                if (layer == 0) {
                    float h0, l0, h1, l1;
                    split1(v0.x, h0, l0); split1(v0.y, h1, l1);
                    g_a1_hi[(size_t)r0 * 128 + (cc >> 1)] = pack2(h0, h1);
                    g_a1_lo[(size_t)r0 * 128 + (cc >> 1)] = pack2(l0, l1);
                }
            }
            if (r0 + 8 < M) {
                *(float2*)(out + (size_t)(r0 + 8) * 256 + cc) = v1;
                if (layer == 0) {
                    float h0, l0, h1, l1;
                    split1(v1.x, h0, l0); split1(v1.y, h1, l1);
                    g_a1_hi[(size_t)(r0 + 8) * 128 + (cc >> 1)] = pack2(h0, h1);
                    g_a1_lo[(size_t)(r0 + 8) * 128 + (cc >> 1)] = pack2(l0, l1);
                }
            }
        }
    }
}

// ---------------------------------------------------------------------------
extern "C" void kernel_launch(void* const* d_in, const int* in_sizes, int n_in,
                              void* d_out, int out_size) {
    const float* feat = (const float*)d_in[0];
    const int*   src  = (const int*)d_in[1];
    const int*   dst  = (const int*)d_in[2];
    const float* Ws0  = (const float*)d_in[3];
    const float* Wn0  = (const float*)d_in[4];
    const float* b0   = (const float*)d_in[5];
    const float* Ws1  = (const float*)d_in[6];
    const float* Wn1  = (const float*)d_in[7];
    const float* b1   = (const float*)d_in[8];

    int N = in_sizes[0] / D;   // 100000
    int E = in_sizes[1];       // 1600000

    float* out0 = (float*)d_out;
    float* a1   = out0 + (size_t)N * D;
    float* h2   = out0 + 2 * (size_t)N * D;

    int nd4 = N * (D / 4);
    int nb = (N + SCAN_BLK - 1) / SCAN_BLK;

    cudaFuncSetAttribute(sage_gemm_kernel,
                         cudaFuncAttributeMaxDynamicSharedMemorySize, SMEM_BYTES);

    // weight transpose+split (tiny)
    wconv_kernel<<<(256 * 256 + 255) / 256, 256>>>(Ws0, Wn0, 0);
    wconv_kernel<<<(256 * 256 + 255) / 256, 256>>>(Ws1, Wn1, 1);

    // CSR build
    zero_cnt_kernel<<<(N + 255) / 256, 256>>>(N);
    hist_kernel<<<(E + 255) / 256, 256>>>(dst, E);
    scan_blocks_kernel<<<nb, SCAN_BLK>>>(N);
    scan_bsums_kernel<<<1, 32>>>(nb);
    scan_add_kernel<<<(N + 255) / 256, 256>>>(N, E);
    fill_kernel<<<(E + 255) / 256, 256>>>(src, dst, E);

    // out[0] = feat; also split feat -> bf16 hi/lo
    copy_convert_kernel<<<(nd4 + 255) / 256, 256>>>(feat, out0, nd4);

    dim3 ggrid(D / 64, (N + 127) / 128);

    // Layer 1
    gather_kernel<<<(N + 7) / 8, 256>>>(feat, N);
    sage_gemm_kernel<<<ggrid, 256, SMEM_BYTES>>>(b0, a1, N, 0, 1);

    // Layer 2
    gather_kernel<<<(N + 7) / 8, 256>>>(a1, N);
    sage_gemm_kernel<<<ggrid, 256, SMEM_BYTES>>>(b1, h2, N, 1, 0);
}

// round 7
// speedup vs baseline: 2.7414x; 1.0671x over previous
#include <cuda_runtime.h>
#include <cuda_bf16.h>
#include <cstddef>
#include <cstdint>

#define D 256
#define N_MAX 100000
#define E_MAX 1600000
#define SCAN_BLK 1024

// ---- scratch (__device__ globals; allocation-free rule) ----
__device__ uint32_t g_feat_hi[(size_t)N_MAX * 128];  // bf16x2 words, [row][128]
__device__ uint32_t g_feat_lo[(size_t)N_MAX * 128];
__device__ uint32_t g_a1_hi[(size_t)N_MAX * 128];
__device__ uint32_t g_a1_lo[(size_t)N_MAX * 128];
__device__ uint32_t g_nhi[(size_t)N_MAX * 128];
__device__ uint32_t g_nlo[(size_t)N_MAX * 128];
__device__ uint32_t g_wthi[2][256 * 256];            // W^T: [n][512k as 256 words]
__device__ uint32_t g_wtlo[2][256 * 256];
__device__ int g_cnt[N_MAX];
__device__ int g_off[N_MAX + 1];
__device__ int g_cursor[N_MAX];
__device__ int g_bsum[(N_MAX + SCAN_BLK - 1) / SCAN_BLK + 1];
__device__ int g_esrc[E_MAX];

// ---- bf16 split helpers ----
__device__ __forceinline__ void split1(float x, float& h, float& l) {
    h = __bfloat162float(__float2bfloat16(x));
    l = x - h;
}
__device__ __forceinline__ uint32_t pack2(float lo_elem, float hi_elem) {
    __nv_bfloat162 t = __floats2bfloat162_rn(lo_elem, hi_elem);
    return *reinterpret_cast<uint32_t*>(&t);
}
__device__ __forceinline__ void split4(float4 v, uint32_t* hw, uint32_t* lw) {
    float h0, l0, h1, l1, h2, l2, h3, l3;
    split1(v.x, h0, l0); split1(v.y, h1, l1);
    split1(v.z, h2, l2); split1(v.w, h3, l3);
    hw[0] = pack2(h0, h1); hw[1] = pack2(h2, h3);
    lw[0] = pack2(l0, l1); lw[1] = pack2(l2, l3);
}

// ---------------------------------------------------------------------------
// copy feat -> out[0], split to g_feat_hi/lo, AND zero g_cnt (fused)
__global__ void copy_convert_kernel(const float* __restrict__ in,
                                    float* __restrict__ out, int n4, int N) {
    int i = blockIdx.x * blockDim.x + threadIdx.x;
    if (i < N) g_cnt[i] = 0;
    if (i >= n4) return;
    float4 v = ((const float4*)in)[i];
    ((float4*)out)[i] = v;
    uint32_t hw[2], lw[2];
    split4(v, hw, lw);
    *(uint2*)&g_feat_hi[(size_t)i * 2] = make_uint2(hw[0], hw[1]);
    *(uint2*)&g_feat_lo[(size_t)i * 2] = make_uint2(lw[0], lw[1]);
}

__global__ void hist_kernel(const int* __restrict__ dst, int E) {
    int i = blockIdx.x * blockDim.x + threadIdx.x;
    if (i < E) atomicAdd(&g_cnt[dst[i]], 1);
}

__global__ void scan_blocks_kernel(int n) {
    __shared__ int sm[SCAN_BLK];
    int tid = threadIdx.x;
    int i = blockIdx.x * SCAN_BLK + tid;
    int v = (i < n) ? g_cnt[i] : 0;
    sm[tid] = v;
    __syncthreads();
#pragma unroll
    for (int off = 1; off < SCAN_BLK; off <<= 1) {
        int t = (tid >= off) ? sm[tid - off] : 0;
        __syncthreads();
        sm[tid] += t;
        __syncthreads();
    }
    if (i < n) g_off[i] = sm[tid] - v;
    if (tid == SCAN_BLK - 1) g_bsum[blockIdx.x] = sm[tid];
}

// scan_add with inline bsum prefix (first warp sums g_bsum[0..g))
__global__ void scan_add_kernel(int n, int E) {
    __shared__ int pref;
    int g = (blockIdx.x * 256) >> 10;   // 256-thread blocks are 1024-aligned chunks
    if (threadIdx.x < 32) {
        int s = 0;
        for (int j = threadIdx.x; j < g; j += 32) s += g_bsum[j];
#pragma unroll
        for (int o = 16; o; o >>= 1) s += __shfl_down_sync(0xFFFFFFFFu, s, o);
        if (threadIdx.x == 0) pref = s;
    }
    __syncthreads();
    int i = blockIdx.x * 256 + threadIdx.x;
    if (i < n) {
        int v = g_off[i] + pref;
        g_off[i] = v;
        g_cursor[i] = v;
    }
    if (i == 0) g_off[n] = E;
}

__global__ void fill_kernel(const int* __restrict__ src,
                            const int* __restrict__ dst, int E) {
    int e = blockIdx.x * blockDim.x + threadIdx.x;
    if (e < E) {
        int d = dst[e];
        int p = atomicAdd(&g_cursor[d], 1);
        g_esrc[p] = src[e];
    }
}

// transpose + split weights, both layers in one launch (grid.y = layer)
__global__ void wconv_kernel(const float* __restrict__ Ws0, const float* __restrict__ Wn0,
                             const float* __restrict__ Ws1, const float* __restrict__ Wn1) {
    int idx = blockIdx.x * blockDim.x + threadIdx.x;
    if (idx >= 256 * 256) return;
    int layer = blockIdx.y;
    const float* Ws = layer ? Ws1 : Ws0;
    const float* Wn = layer ? Wn1 : Wn0;
    int n = idx & 255;
    int wp = idx >> 8;
    int k0 = wp * 2, k1 = k0 + 1;
    float v0 = (k0 < 256) ? Ws[k0 * 256 + n] : Wn[(k0 - 256) * 256 + n];
    float v1 = (k1 < 256) ? Ws[k1 * 256 + n] : Wn[(k1 - 256) * 256 + n];
    float h0, l0, h1, l1;
    split1(v0, h0, l0);
    split1(v1, h1, l1);
    g_wthi[layer][n * 256 + wp] = pack2(h0, h1);
    g_wtlo[layer][n * 256 + wp] = pack2(l0, l1);
}

// ---------------------------------------------------------------------------
// Gather aggregation: one warp per dst node; outputs bf16 hi/lo words.
__global__ void gather_kernel(const float* __restrict__ X, int N) {
    int node = blockIdx.x * 8 + (threadIdx.x >> 5);
    if (node >= N) return;
    int lane = threadIdx.x & 31;

    int beg = g_off[node];
    int end = g_off[node + 1];

    float4 a0 = make_float4(0.f, 0.f, 0.f, 0.f);
    float4 a1 = make_float4(0.f, 0.f, 0.f, 0.f);

    int i = beg;
    for (; i + 1 < end; i += 2) {
        int s0 = __ldg(g_esrc + i);
        int s1 = __ldg(g_esrc + i + 1);
        const float4* x0 = (const float4*)(X + (size_t)s0 * D);
        const float4* x1 = (const float4*)(X + (size_t)s1 * D);
        float4 v00 = __ldg(x0 + lane);
        float4 v01 = __ldg(x0 + lane + 32);
        float4 v10 = __ldg(x1 + lane);
        float4 v11 = __ldg(x1 + lane + 32);
        a0.x += v00.x + v10.x; a0.y += v00.y + v10.y;
        a0.z += v00.z + v10.z; a0.w += v00.w + v10.w;
        a1.x += v01.x + v11.x; a1.y += v01.y + v11.y;
        a1.z += v01.z + v11.z; a1.w += v01.w + v11.w;
    }
    if (i < end) {
        int s0 = __ldg(g_esrc + i);
        const float4* x0 = (const float4*)(X + (size_t)s0 * D);
        float4 v00 = __ldg(x0 + lane);
        float4 v01 = __ldg(x0 + lane + 32);
        a0.x += v00.x; a0.y += v00.y; a0.z += v00.z; a0.w += v00.w;
        a1.x += v01.x; a1.y += v01.y; a1.z += v01.z; a1.w += v01.w;
    }

    float inv = (end > beg) ? (1.0f / (float)(end - beg)) : 0.f;
    a0.x *= inv; a0.y *= inv; a0.z *= inv; a0.w *= inv;
    a1.x *= inv; a1.y *= inv; a1.z *= inv; a1.w *= inv;

    uint32_t hw[2], lw[2];
    size_t base = (size_t)node * 128;
    split4(a0, hw, lw);
    *(uint2*)&g_nhi[base + lane * 2] = make_uint2(hw[0], hw[1]);
    *(uint2*)&g_nlo[base + lane * 2] = make_uint2(lw[0], lw[1]);
    split4(a1, hw, lw);
    *(uint2*)&g_nhi[base + 64 + lane * 2] = make_uint2(hw[0], hw[1]);
    *(uint2*)&g_nlo[base + 64 + lane * 2] = make_uint2(lw[0], lw[1]);
}

// ---------------------------------------------------------------------------
// Split-BF16 tensor GEMM with ldmatrix fragment loads.
#define T_STR 20
#define SA_SZ (128 * T_STR)
#define SB_SZ (64 * T_STR)
#define SMEM_WORDS (2 * (2 * SA_SZ + 2 * SB_SZ))
#define SMEM_BYTES (SMEM_WORDS * 4)

__device__ __forceinline__ void cp_async16(void* s, const void* g, bool pred) {
    uint32_t sa = (uint32_t)__cvta_generic_to_shared(s);
    int sz = pred ? 16 : 0;
    asm volatile("cp.async.cg.shared.global [%0], [%1], 16, %2;"
                 :: "r"(sa), "l"(g), "r"(sz) : "memory");
}

__device__ __forceinline__ void mma_bf16(float* c, const uint32_t* a, const uint32_t* b) {
    asm volatile(
        "mma.sync.aligned.m16n8k16.row.col.f32.bf16.bf16.f32 "
        "{%0,%1,%2,%3}, {%4,%5,%6,%7}, {%8,%9}, {%0,%1,%2,%3};"
        : "+f"(c[0]), "+f"(c[1]), "+f"(c[2]), "+f"(c[3])
        : "r"(a[0]), "r"(a[1]), "r"(a[2]), "r"(a[3]), "r"(b[0]), "r"(b[1]));
}

__device__ __forceinline__ void ldsm_x4(uint32_t* r, uint32_t addr) {
    asm volatile("ldmatrix.sync.aligned.m8n8.x4.shared.b16 {%0,%1,%2,%3}, [%4];"
                 : "=r"(r[0]), "=r"(r[1]), "=r"(r[2]), "=r"(r[3]) : "r"(addr));
}

__global__ void __launch_bounds__(256) sage_gemm_kernel(
    const float* __restrict__ bias,
    float* __restrict__ out,
    int M, int layer, int do_relu) {
    extern __shared__ uint32_t smem[];
    uint32_t* sAh = smem;
    uint32_t* sAl = smem + 2 * SA_SZ;
    uint32_t* sBh = smem + 4 * SA_SZ;
    uint32_t* sBl = smem + 4 * SA_SZ + 2 * SB_SZ;
    const uint32_t smem_u32 = (uint32_t)__cvta_generic_to_shared(smem);

    const int tid = threadIdx.x;
    const int lane = tid & 31;
    const int wid = tid >> 5;
    const int wm = wid >> 1;
    const int wn = wid & 1;
    const int bm = blockIdx.y * 128;
    const int bn = blockIdx.x * 64;

    const uint32_t* Xhi = layer ? g_a1_hi : g_feat_hi;
    const uint32_t* Xlo = layer ? g_a1_lo : g_feat_lo;
    const uint32_t* Whi = g_wthi[layer];
    const uint32_t* Wlo = g_wtlo[layer];

    float acc[2][4][4] = {};

    auto load_tile = [&](int it, int buf) {
        int kg = it * 32;
        const uint32_t* Ah = (kg < 256) ? Xhi : (const uint32_t*)g_nhi;
        const uint32_t* Al = (kg < 256) ? Xlo : (const uint32_t*)g_nlo;
        int klw = (kg & 255) >> 1;
        uint32_t* dAh = sAh + buf * SA_SZ;
        uint32_t* dAl = sAl + buf * SA_SZ;
        uint32_t* dBh = sBh + buf * SB_SZ;
        uint32_t* dBl = sBl + buf * SB_SZ;
#pragma unroll
        for (int i = 0; i < 2; ++i) {
            int ci = i * 256 + tid;
            int row = ci >> 2, ch = ci & 3;
            int grow = bm + row;
            bool ok = grow < M;
            size_t off = (size_t)(ok ? grow : (M - 1)) * 128 + klw + ch * 4;
            cp_async16(dAh + row * T_STR + ch * 4, Ah + off, ok);
            cp_async16(dAl + row * T_STR + ch * 4, Al + off, ok);
        }
        {
            int row = tid >> 2, ch = tid & 3;
            size_t off = (size_t)(bn + row) * 256 + it * 16 + ch * 4;
            cp_async16(dBh + row * T_STR + ch * 4, Whi + off, true);
            cp_async16(dBl + row * T_STR + ch * 4, Wlo + off, true);
        }
    };

    load_tile(0, 0);
    asm volatile("cp.async.commit_group;" ::: "memory");

    // per-lane ldmatrix address components (constant across iters)
    const int a_r = wm * 32 + (lane & 15);          // + mt*16
    const int a_w = (lane >> 4) << 2;               // + ks*8
    const int b_r = wn * 32 + (lane & 7) + ((lane >> 4) << 3);  // + np*16
    const int b_w = ((lane >> 3) & 1) << 2;         // + ks*8

    const int K_ITERS = 512 / 32;  // 16
#pragma unroll 1
    for (int it = 0; it < K_ITERS; ++it) {
        if (it + 1 < K_ITERS) {
            load_tile(it + 1, (it + 1) & 1);
            asm volatile("cp.async.commit_group;" ::: "memory");
            asm volatile("cp.async.wait_group 1;" ::: "memory");
        } else {
            asm volatile("cp.async.wait_group 0;" ::: "memory");
        }
        __syncthreads();

        const uint32_t aHb = smem_u32 + ((it & 1) * SA_SZ) * 4;
        const uint32_t aLb = aHb + (2 * SA_SZ) * 4;
        const uint32_t bHb = smem_u32 + (4 * SA_SZ + (it & 1) * SB_SZ) * 4;
        const uint32_t bLb = bHb + (2 * SB_SZ) * 4;

#pragma unroll
        for (int ks = 0; ks < 2; ++ks) {
            uint32_t ah[2][4], al[2][4], bh[4][2], bl[4][2];
#pragma unroll
            for (int mt = 0; mt < 2; ++mt) {
                uint32_t off = (uint32_t)(((a_r + mt * 16) * T_STR + a_w + ks * 8) * 4);
                ldsm_x4(ah[mt], aHb + off);
                ldsm_x4(al[mt], aLb + off);
            }
#pragma unroll
            for (int np = 0; np < 2; ++np) {
                uint32_t off = (uint32_t)(((b_r + np * 16) * T_STR + b_w + ks * 8) * 4);
                uint32_t t[4];
                ldsm_x4(t, bHb + off);
                bh[np * 2][0] = t[0]; bh[np * 2][1] = t[1];
                bh[np * 2 + 1][0] = t[2]; bh[np * 2 + 1][1] = t[3];
                ldsm_x4(t, bLb + off);
                bl[np * 2][0] = t[0]; bl[np * 2][1] = t[1];
                bl[np * 2 + 1][0] = t[2]; bl[np * 2 + 1][1] = t[3];
            }
#pragma unroll
            for (int mt = 0; mt < 2; ++mt)
#pragma unroll
                for (int nt = 0; nt < 4; ++nt) {
                    mma_bf16(acc[mt][nt], ah[mt], bl[nt]);
                    mma_bf16(acc[mt][nt], al[mt], bh[nt]);
                    mma_bf16(acc[mt][nt], ah[mt], bh[nt]);
                }
        }
        __syncthreads();
    }

    // ---- epilogue: bias (+relu); layer 0 also writes a1 hi/lo bf16 ----
#pragma unroll
    for (int mt = 0; mt < 2; ++mt) {
        int r0 = bm + wm * 32 + mt * 16 + (lane >> 2);
#pragma unroll
        for (int nt = 0; nt < 4; ++nt) {
            int cc = bn + wn * 32 + nt * 8 + (lane & 3) * 2;
            float bx = __ldg(bias + cc);
            float by = __ldg(bias + cc + 1);
            float2 v0, v1;
            v0.x = acc[mt][nt][0] + bx; v0.y = acc[mt][nt][1] + by;
            v1.x = acc[mt][nt][2] + bx; v1.y = acc[mt][nt][3] + by;
            if (do_relu) {
                v0.x = fmaxf(v0.x, 0.f); v0.y = fmaxf(v0.y, 0.f);
                v1.x = fmaxf(v1.x, 0.f); v1.y = fmaxf(v1.y, 0.f);
            }
            if (r0 < M) {
                *(float2*)(out + (size_t)r0 * 256 + cc) = v0;
                if (layer == 0) {
                    float h0, l0, h1, l1;
                    split1(v0.x, h0, l0); split1(v0.y, h1, l1);
                    g_a1_hi[(size_t)r0 * 128 + (cc >> 1)] = pack2(h0, h1);
                    g_a1_lo[(size_t)r0 * 128 + (cc >> 1)] = pack2(l0, l1);
                }
            }
            if (r0 + 8 < M) {
                *(float2*)(out + (size_t)(r0 + 8) * 256 + cc) = v1;
                if (layer == 0) {
                    float h0, l0, h1, l1;
                    split1(v1.x, h0, l0); split1(v1.y, h1, l1);
                    g_a1_hi[(size_t)(r0 + 8) * 128 + (cc >> 1)] = pack2(h0, h1);
                    g_a1_lo[(size_t)(r0 + 8) * 128 + (cc >> 1)] = pack2(l0, l1);
                }
            }
        }
    }
}

// ---------------------------------------------------------------------------
extern "C" void kernel_launch(void* const* d_in, const int* in_sizes, int n_in,
                              void* d_out, int out_size) {
    const float* feat = (const float*)d_in[0];
    const int*   src  = (const int*)d_in[1];
    const int*   dst  = (const int*)d_in[2];
    const float* Ws0  = (const float*)d_in[3];
    const float* Wn0  = (const float*)d_in[4];
    const float* b0   = (const float*)d_in[5];
    const float* Ws1  = (const float*)d_in[6];
    const float* Wn1  = (const float*)d_in[7];
    const float* b1   = (const float*)d_in[8];

    int N = in_sizes[0] / D;   // 100000
    int E = in_sizes[1];       // 1600000

    float* out0 = (float*)d_out;
    float* a1   = out0 + (size_t)N * D;
    float* h2   = out0 + 2 * (size_t)N * D;

    int nd4 = N * (D / 4);
    int nb = (N + SCAN_BLK - 1) / SCAN_BLK;

    cudaFuncSetAttribute(sage_gemm_kernel,
                         cudaFuncAttributeMaxDynamicSharedMemorySize, SMEM_BYTES);

    // 0: copy feat -> out[0], split to bf16, zero g_cnt
    copy_convert_kernel<<<(nd4 + 255) / 256, 256>>>(feat, out0, nd4, N);
    // 1-4: CSR build
    hist_kernel<<<(E + 255) / 256, 256>>>(dst, E);
    scan_blocks_kernel<<<nb, SCAN_BLK>>>(N);
    scan_add_kernel<<<(N + 255) / 256, 256>>>(N, E);
    fill_kernel<<<(E + 255) / 256, 256>>>(src, dst, E);

    // 5: gather layer 1 (lands at ncu profile index 5)
    gather_kernel<<<(N + 7) / 8, 256>>>(feat, N);

    // 6: weight transpose+split (both layers)
    wconv_kernel<<<dim3((256 * 256 + 255) / 256, 2), 256>>>(Ws0, Wn0, Ws1, Wn1);

    dim3 ggrid(D / 64, (N + 127) / 128);

    // 7: GEMM layer 1
    sage_gemm_kernel<<<ggrid, 256, SMEM_BYTES>>>(b0, a1, N, 0, 1);
    // 8: gather layer 2
    gather_kernel<<<(N + 7) / 8, 256>>>(a1, N);
    // 9: GEMM layer 2
    sage_gemm_kernel<<<ggrid, 256, SMEM_BYTES>>>(b1, h2, N, 1, 0);
}

// round 9
// speedup vs baseline: 2.7514x; 1.0037x over previous
#include <cuda_runtime.h>
#include <cuda_bf16.h>
#include <cstddef>
#include <cstdint>

#define D 256
#define N_MAX 100000
#define E_MAX 1600000
#define SCAN_BLK 1024

// NOTE (R8 lesson): harness PTX targets compute_103 (no 'a') -> tcgen05/kind::f16
// are ptxas-rejected. Legacy mma.sync is the only tensor path available here.

// ---- scratch (__device__ globals; allocation-free rule) ----
__device__ uint32_t g_feat_hi[(size_t)N_MAX * 128];  // bf16x2 words, [row][128]
__device__ uint32_t g_feat_lo[(size_t)N_MAX * 128];
__device__ uint32_t g_a1_hi[(size_t)N_MAX * 128];
__device__ uint32_t g_a1_lo[(size_t)N_MAX * 128];
__device__ uint32_t g_nhi[(size_t)N_MAX * 128];
__device__ uint32_t g_nlo[(size_t)N_MAX * 128];
__device__ uint32_t g_wthi[2][256 * 256];            // W^T: [n][512k as 256 words]
__device__ uint32_t g_wtlo[2][256 * 256];
__device__ int g_cnt[N_MAX];
__device__ int g_off[N_MAX + 1];
__device__ int g_cursor[N_MAX];
__device__ int g_bsum[(N_MAX + SCAN_BLK - 1) / SCAN_BLK + 1];
__device__ int g_esrc[E_MAX];

// ---- bf16 split helpers ----
__device__ __forceinline__ void split1(float x, float& h, float& l) {
    h = __bfloat162float(__float2bfloat16(x));
    l = x - h;
}
__device__ __forceinline__ uint32_t pack2(float lo_elem, float hi_elem) {
    __nv_bfloat162 t = __floats2bfloat162_rn(lo_elem, hi_elem);
    return *reinterpret_cast<uint32_t*>(&t);
}
__device__ __forceinline__ void split4(float4 v, uint32_t* hw, uint32_t* lw) {
    float h0, l0, h1, l1, h2, l2, h3, l3;
    split1(v.x, h0, l0); split1(v.y, h1, l1);
    split1(v.z, h2, l2); split1(v.w, h3, l3);
    hw[0] = pack2(h0, h1); hw[1] = pack2(h2, h3);
    lw[0] = pack2(l0, l1); lw[1] = pack2(l2, l3);
}

// ---------------------------------------------------------------------------
__global__ void copy_convert_kernel(const float* __restrict__ in,
                                    float* __restrict__ out, int n4, int N) {
    int i = blockIdx.x * blockDim.x + threadIdx.x;
    if (i < N) g_cnt[i] = 0;
    if (i >= n4) return;
    float4 v = ((const float4*)in)[i];
    ((float4*)out)[i] = v;
    uint32_t hw[2], lw[2];
    split4(v, hw, lw);
    *(uint2*)&g_feat_hi[(size_t)i * 2] = make_uint2(hw[0], hw[1]);
    *(uint2*)&g_feat_lo[(size_t)i * 2] = make_uint2(lw[0], lw[1]);
}

__global__ void hist_kernel(const int* __restrict__ dst, int E) {
    int i = blockIdx.x * blockDim.x + threadIdx.x;
    if (i < E) atomicAdd(&g_cnt[dst[i]], 1);
}

__global__ void scan_blocks_kernel(int n) {
    __shared__ int sm[SCAN_BLK];
    int tid = threadIdx.x;
    int i = blockIdx.x * SCAN_BLK + tid;
    int v = (i < n) ? g_cnt[i] : 0;
    sm[tid] = v;
    __syncthreads();
#pragma unroll
    for (int off = 1; off < SCAN_BLK; off <<= 1) {
        int t = (tid >= off) ? sm[tid - off] : 0;
        __syncthreads();
        sm[tid] += t;
        __syncthreads();
    }
    if (i < n) g_off[i] = sm[tid] - v;
    if (tid == SCAN_BLK - 1) g_bsum[blockIdx.x] = sm[tid];
}

__global__ void scan_add_kernel(int n, int E) {
    __shared__ int pref;
    int g = (blockIdx.x * 256) >> 10;
    if (threadIdx.x < 32) {
        int s = 0;
        for (int j = threadIdx.x; j < g; j += 32) s += g_bsum[j];
#pragma unroll
        for (int o = 16; o; o >>= 1) s += __shfl_down_sync(0xFFFFFFFFu, s, o);
        if (threadIdx.x == 0) pref = s;
    }
    __syncthreads();
    int i = blockIdx.x * 256 + threadIdx.x;
    if (i < n) {
        int v = g_off[i] + pref;
        g_off[i] = v;
        g_cursor[i] = v;
    }
    if (i == 0) g_off[n] = E;
}

__global__ void fill_kernel(const int* __restrict__ src,
                            const int* __restrict__ dst, int E) {
    int e = blockIdx.x * blockDim.x + threadIdx.x;
    if (e < E) {
        int d = dst[e];
        int p = atomicAdd(&g_cursor[d], 1);
        g_esrc[p] = src[e];
    }
}

__global__ void wconv_kernel(const float* __restrict__ Ws0, const float* __restrict__ Wn0,
                             const float* __restrict__ Ws1, const float* __restrict__ Wn1) {
    int idx = blockIdx.x * blockDim.x + threadIdx.x;
    if (idx >= 256 * 256) return;
    int layer = blockIdx.y;
    const float* Ws = layer ? Ws1 : Ws0;
    const float* Wn = layer ? Wn1 : Wn0;
    int n = idx & 255;
    int wp = idx >> 8;
    int k0 = wp * 2, k1 = k0 + 1;
    float v0 = (k0 < 256) ? Ws[k0 * 256 + n] : Wn[(k0 - 256) * 256 + n];
    float v1 = (k1 < 256) ? Ws[k1 * 256 + n] : Wn[(k1 - 256) * 256 + n];
    float h0, l0, h1, l1;
    split1(v0, h0, l0);
    split1(v1, h1, l1);
    g_wthi[layer][n * 256 + wp] = pack2(h0, h1);
    g_wtlo[layer][n * 256 + wp] = pack2(l0, l1);
}

// ---------------------------------------------------------------------------
__global__ void gather_kernel(const float* __restrict__ X, int N) {
    int node = blockIdx.x * 8 + (threadIdx.x >> 5);
    if (node >= N) return;
    int lane = threadIdx.x & 31;

    int beg = g_off[node];
    int end = g_off[node + 1];

    float4 a0 = make_float4(0.f, 0.f, 0.f, 0.f);
    float4 a1 = make_float4(0.f, 0.f, 0.f, 0.f);

    int i = beg;
    for (; i + 1 < end; i += 2) {
        int s0 = __ldg(g_esrc + i);
        int s1 = __ldg(g_esrc + i + 1);
        const float4* x0 = (const float4*)(X + (size_t)s0 * D);
        const float4* x1 = (const float4*)(X + (size_t)s1 * D);
        float4 v00 = __ldg(x0 + lane);
        float4 v01 = __ldg(x0 + lane + 32);
        float4 v10 = __ldg(x1 + lane);
        float4 v11 = __ldg(x1 + lane + 32);
        a0.x += v00.x + v10.x; a0.y += v00.y + v10.y;
        a0.z += v00.z + v10.z; a0.w += v00.w + v10.w;
        a1.x += v01.x + v11.x; a1.y += v01.y + v11.y;
        a1.z += v01.z + v11.z; a1.w += v01.w + v11.w;
    }
    if (i < end) {
        int s0 = __ldg(g_esrc + i);
        const float4* x0 = (const float4*)(X + (size_t)s0 * D);
        float4 v00 = __ldg(x0 + lane);
        float4 v01 = __ldg(x0 + lane + 32);
        a0.x += v00.x; a0.y += v00.y; a0.z += v00.z; a0.w += v00.w;
        a1.x += v01.x; a1.y += v01.y; a1.z += v01.z; a1.w += v01.w;
    }

    float inv = (end > beg) ? (1.0f / (float)(end - beg)) : 0.f;
    a0.x *= inv; a0.y *= inv; a0.z *= inv; a0.w *= inv;
    a1.x *= inv; a1.y *= inv; a1.z *= inv; a1.w *= inv;

    uint32_t hw[2], lw[2];
    size_t base = (size_t)node * 128;
    split4(a0, hw, lw);
    *(uint2*)&g_nhi[base + lane * 2] = make_uint2(hw[0], hw[1]);
    *(uint2*)&g_nlo[base + lane * 2] = make_uint2(lw[0], lw[1]);
    split4(a1, hw, lw);
    *(uint2*)&g_nhi[base + 64 + lane * 2] = make_uint2(hw[0], hw[1]);
    *(uint2*)&g_nlo[base + 64 + lane * 2] = make_uint2(lw[0], lw[1]);
}

// ---------------------------------------------------------------------------
// Split-BF16 tensor GEMM (ldmatrix), CTA tile 128x128, warp tile 32x64.
// Per warp per BK=32 iter: 24 LDSM.x4 + 96 MMA (was 16+48 for half the output).
#define T_STR 20
#define SA_SZ (128 * T_STR)
#define SB_SZ (128 * T_STR)
#define SMEM_WORDS (2 * (2 * SA_SZ + 2 * SB_SZ))
#define SMEM_BYTES (SMEM_WORDS * 4)

__device__ __forceinline__ void cp_async16(void* s, const void* g, bool pred) {
    uint32_t sa = (uint32_t)__cvta_generic_to_shared(s);
    int sz = pred ? 16 : 0;
    asm volatile("cp.async.cg.shared.global [%0], [%1], 16, %2;"
                 :: "r"(sa), "l"(g), "r"(sz) : "memory");
}

__device__ __forceinline__ void mma_bf16(float* c, const uint32_t* a, const uint32_t* b) {
    asm volatile(
        "mma.sync.aligned.m16n8k16.row.col.f32.bf16.bf16.f32 "
        "{%0,%1,%2,%3}, {%4,%5,%6,%7}, {%8,%9}, {%0,%1,%2,%3};"
        : "+f"(c[0]), "+f"(c[1]), "+f"(c[2]), "+f"(c[3])
        : "r"(a[0]), "r"(a[1]), "r"(a[2]), "r"(a[3]), "r"(b[0]), "r"(b[1]));
}

__device__ __forceinline__ void ldsm_x4(uint32_t* r, uint32_t addr) {
    asm volatile("ldmatrix.sync.aligned.m8n8.x4.shared.b16 {%0,%1,%2,%3}, [%4];"
                 : "=r"(r[0]), "=r"(r[1]), "=r"(r[2]), "=r"(r[3]) : "r"(addr));
}

__global__ void __launch_bounds__(256) sage_gemm_kernel(
    const float* __restrict__ bias,
    float* __restrict__ out,
    int M, int layer, int do_relu) {
    extern __shared__ uint32_t smem[];
    uint32_t* sAh = smem;
    uint32_t* sAl = smem + 2 * SA_SZ;
    uint32_t* sBh = smem + 4 * SA_SZ;
    uint32_t* sBl = smem + 4 * SA_SZ + 2 * SB_SZ;
    const uint32_t smem_u32 = (uint32_t)__cvta_generic_to_shared(smem);

    const int tid = threadIdx.x;
    const int lane = tid & 31;
    const int wid = tid >> 5;
    const int wm = wid >> 1;          // 0..3  (m32 each)
    const int wn = wid & 1;           // 0..1  (n64 each)
    const int bm = blockIdx.y * 128;
    const int bn = blockIdx.x * 128;

    const uint32_t* Xhi = layer ? g_a1_hi : g_feat_hi;
    const uint32_t* Xlo = layer ? g_a1_lo : g_feat_lo;
    const uint32_t* Whi = g_wthi[layer];
    const uint32_t* Wlo = g_wtlo[layer];

    float acc[2][8][4] = {};

    auto load_tile = [&](int it, int buf) {
        int kg = it * 32;
        const uint32_t* Ah = (kg < 256) ? Xhi : (const uint32_t*)g_nhi;
        const uint32_t* Al = (kg < 256) ? Xlo : (const uint32_t*)g_nlo;
        int klw = (kg & 255) >> 1;
        uint32_t* dAh = sAh + buf * SA_SZ;
        uint32_t* dAl = sAl + buf * SA_SZ;
        uint32_t* dBh = sBh + buf * SB_SZ;
        uint32_t* dBl = sBl + buf * SB_SZ;
#pragma unroll
        for (int i = 0; i < 2; ++i) {            // A: 128 rows x 4 chunks
            int ci = i * 256 + tid;
            int row = ci >> 2, ch = ci & 3;
            int grow = bm + row;
            bool ok = grow < M;
            size_t off = (size_t)(ok ? grow : (M - 1)) * 128 + klw + ch * 4;
            cp_async16(dAh + row * T_STR + ch * 4, Ah + off, ok);
            cp_async16(dAl + row * T_STR + ch * 4, Al + off, ok);
        }
#pragma unroll
        for (int i = 0; i < 2; ++i) {            // B: 128 rows x 4 chunks
            int ci = i * 256 + tid;
            int row = ci >> 2, ch = ci & 3;
            size_t off = (size_t)(bn + row) * 256 + it * 16 + ch * 4;
            cp_async16(dBh + row * T_STR + ch * 4, Whi + off, true);
            cp_async16(dBl + row * T_STR + ch * 4, Wlo + off, true);
        }
    };

    load_tile(0, 0);
    asm volatile("cp.async.commit_group;" ::: "memory");

    const int a_r = wm * 32 + (lane & 15);
    const int a_w = (lane >> 4) << 2;
    const int b_r = wn * 64 + (lane & 7) + ((lane >> 4) << 3);
    const int b_w = ((lane >> 3) & 1) << 2;

    const int K_ITERS = 512 / 32;  // 16
#pragma unroll 1
    for (int it = 0; it < K_ITERS; ++it) {
        if (it + 1 < K_ITERS) {
            load_tile(it + 1, (it + 1) & 1);
            asm volatile("cp.async.commit_group;" ::: "memory");
            asm volatile("cp.async.wait_group 1;" ::: "memory");
        } else {
            asm volatile("cp.async.wait_group 0;" ::: "memory");
        }
        __syncthreads();

        const uint32_t aHb = smem_u32 + ((it & 1) * SA_SZ) * 4;
        const uint32_t aLb = aHb + (2 * SA_SZ) * 4;
        const uint32_t bHb = smem_u32 + (4 * SA_SZ + (it & 1) * SB_SZ) * 4;
        const uint32_t bLb = bHb + (2 * SB_SZ) * 4;

#pragma unroll
        for (int ks = 0; ks < 2; ++ks) {
            uint32_t ah[2][4], al[2][4], bh[8][2], bl[8][2];
#pragma unroll
            for (int mt = 0; mt < 2; ++mt) {
                uint32_t off = (uint32_t)(((a_r + mt * 16) * T_STR + a_w + ks * 8) * 4);
                ldsm_x4(ah[mt], aHb + off);
                ldsm_x4(al[mt], aLb + off);
            }
#pragma unroll
            for (int np = 0; np < 4; ++np) {
                uint32_t off = (uint32_t)(((b_r + np * 16) * T_STR + b_w + ks * 8) * 4);
                uint32_t t[4];
                ldsm_x4(t, bHb + off);
                bh[np * 2][0] = t[0]; bh[np * 2][1] = t[1];
                bh[np * 2 + 1][0] = t[2]; bh[np * 2 + 1][1] = t[3];
                ldsm_x4(t, bLb + off);
                bl[np * 2][0] = t[0]; bl[np * 2][1] = t[1];
                bl[np * 2 + 1][0] = t[2]; bl[np * 2 + 1][1] = t[3];
            }
#pragma unroll
            for (int mt = 0; mt < 2; ++mt)
#pragma unroll
                for (int nt = 0; nt < 8; ++nt) {
                    mma_bf16(acc[mt][nt], ah[mt], bl[nt]);
                    mma_bf16(acc[mt][nt], al[mt], bh[nt]);
                    mma_bf16(acc[mt][nt], ah[mt], bh[nt]);
                }
        }
        __syncthreads();
    }

    // ---- epilogue: bias (+relu); layer 0 also writes a1 hi/lo bf16 ----
#pragma unroll
    for (int mt = 0; mt < 2; ++mt) {
        int r0 = bm + wm * 32 + mt * 16 + (lane >> 2);
#pragma unroll
        for (int nt = 0; nt < 8; ++nt) {
            int cc = bn + wn * 64 + nt * 8 + (lane & 3) * 2;
            float bx = __ldg(bias + cc);
            float by = __ldg(bias + cc + 1);
            float2 v0, v1;
            v0.x = acc[mt][nt][0] + bx; v0.y = acc[mt][nt][1] + by;
            v1.x = acc[mt][nt][2] + bx; v1.y = acc[mt][nt][3] + by;
            if (do_relu) {
                v0.x = fmaxf(v0.x, 0.f); v0.y = fmaxf(v0.y, 0.f);
                v1.x = fmaxf(v1.x, 0.f); v1.y = fmaxf(v1.y, 0.f);
            }
            if (r0 < M) {
                *(float2*)(out + (size_t)r0 * 256 + cc) = v0;
                if (layer == 0) {
                    float h0, l0, h1, l1;
                    split1(v0.x, h0, l0); split1(v0.y, h1, l1);
                    g_a1_hi[(size_t)r0 * 128 + (cc >> 1)] = pack2(h0, h1);
                    g_a1_lo[(size_t)r0 * 128 + (cc >> 1)] = pack2(l0, l1);
                }
            }
            if (r0 + 8 < M) {
                *(float2*)(out + (size_t)(r0 + 8) * 256 + cc) = v1;
                if (layer == 0) {
                    float h0, l0, h1, l1;
                    split1(v1.x, h0, l0); split1(v1.y, h1, l1);
                    g_a1_hi[(size_t)(r0 + 8) * 128 + (cc >> 1)] = pack2(h0, h1);
                    g_a1_lo[(size_t)(r0 + 8) * 128 + (cc >> 1)] = pack2(l0, l1);
                }
            }
        }
    }
}

// ---------------------------------------------------------------------------
extern "C" void kernel_launch(void* const* d_in, const int* in_sizes, int n_in,
                              void* d_out, int out_size) {
    const float* feat = (const float*)d_in[0];
    const int*   src  = (const int*)d_in[1];
    const int*   dst  = (const int*)d_in[2];
    const float* Ws0  = (const float*)d_in[3];
    const float* Wn0  = (const float*)d_in[4];
    const float* b0   = (const float*)d_in[5];
    const float* Ws1  = (const float*)d_in[6];
    const float* Wn1  = (const float*)d_in[7];
    const float* b1   = (const float*)d_in[8];

    int N = in_sizes[0] / D;   // 100000
    int E = in_sizes[1];       // 1600000

    float* out0 = (float*)d_out;
    float* a1   = out0 + (size_t)N * D;
    float* h2   = out0 + 2 * (size_t)N * D;

    int nd4 = N * (D / 4);
    int nb = (N + SCAN_BLK - 1) / SCAN_BLK;

    cudaFuncSetAttribute(sage_gemm_kernel,
                         cudaFuncAttributeMaxDynamicSharedMemorySize, SMEM_BYTES);

    copy_convert_kernel<<<(nd4 + 255) / 256, 256>>>(feat, out0, nd4, N);
    hist_kernel<<<(E + 255) / 256, 256>>>(dst, E);
    scan_blocks_kernel<<<nb, SCAN_BLK>>>(N);
    scan_add_kernel<<<(N + 255) / 256, 256>>>(N, E);
    fill_kernel<<<(E + 255) / 256, 256>>>(src, dst, E);

    gather_kernel<<<(N + 7) / 8, 256>>>(feat, N);

    wconv_kernel<<<dim3((256 * 256 + 255) / 256, 2), 256>>>(Ws0, Wn0, Ws1, Wn1);

    dim3 ggrid(2, (N + 127) / 128);

    sage_gemm_kernel<<<ggrid, 256, SMEM_BYTES>>>(b0, a1, N, 0, 1);
    gather_kernel<<<(N + 7) / 8, 256>>>(a1, N);
    sage_gemm_kernel<<<ggrid, 256, SMEM_BYTES>>>(b1, h2, N, 1, 0);
}